// round 1
// baseline (speedup 1.0000x reference)
#include <cuda_runtime.h>
#include <cuda_bf16.h>
#include <math.h>

// Problem constants
#define B_  2
#define L_  2048
#define D_  256
#define H_  8
#define h_  32
#define C_  128           // chunk size
#define NC_ (L_ / C_)     // 16 chunks per (b,h)
#define BH_ (B_ * H_)     // 16
#define NPOS_ (BH_ * L_)  // 32768
#define EPS_ 1e-5f

// -------- scratch (device globals, no allocation) --------
__device__ float g_Q[NPOS_ * h_];      // [B,H,L,h]
__device__ float g_K[NPOS_ * h_];
__device__ float g_V[NPOS_ * h_];
__device__ float g_sim[NPOS_];
__device__ float g_gate[NPOS_];
__device__ float g_Sdelta[BH_ * NC_ * h_ * h_];
__device__ float g_Sprefix[BH_ * NC_ * h_ * h_];
__device__ float g_gsum[BH_ * NC_];
__device__ float g_mloc[BH_ * NC_];
__device__ float g_sloc[BH_ * NC_];
__device__ float g_gpre[BH_ * NC_];
__device__ float g_mpre[BH_ * NC_];
__device__ float g_spre[BH_ * NC_];
__device__ float g_ctxt[B_ * L_ * D_];  // [B,L,D]

// -------- helpers --------
__device__ __forceinline__ float warpSum(float v) {
#pragma unroll
    for (int o = 16; o > 0; o >>= 1) v += __shfl_xor_sync(0xffffffffu, v, o);
    return v;
}
__device__ __forceinline__ float warpMax(float v) {
#pragma unroll
    for (int o = 16; o > 0; o >>= 1) v = fmaxf(v, __shfl_xor_sync(0xffffffffu, v, o));
    return v;
}

// =====================================================================
// K1/K6: tiled fp32 GEMM:  Out[n,o] = sum_i X[n,i]*W[o,i] + bias[o]
// mode 0: scatter to [B,H,L,h] layout (for q/k/v). mode 1: row-major.
// M=4096, N=256, K=256. Tile 64x64, K-step 32, 256 threads, 4x4/thread.
// =====================================================================
__global__ void gemm_bias_kernel(const float* __restrict__ X,
                                 const float* __restrict__ W,
                                 const float* __restrict__ bias,
                                 float* __restrict__ Out, int mode) {
    __shared__ float xs[64][33];
    __shared__ float ws[64][33];
    const int tx = threadIdx.x & 15;
    const int ty = threadIdx.x >> 4;
    const int rowBase = blockIdx.x * 64;
    const int colBase = blockIdx.y * 64;

    float acc[4][4];
#pragma unroll
    for (int i = 0; i < 4; i++)
#pragma unroll
        for (int j = 0; j < 4; j++) acc[i][j] = 0.f;

    for (int k0 = 0; k0 < D_; k0 += 32) {
#pragma unroll
        for (int i = threadIdx.x; i < 64 * 32; i += 256) {
            int m = i >> 5, kk = i & 31;
            xs[m][kk] = X[(size_t)(rowBase + m) * D_ + k0 + kk];
            ws[m][kk] = W[(size_t)(colBase + m) * D_ + k0 + kk];
        }
        __syncthreads();
#pragma unroll
        for (int kk = 0; kk < 32; kk++) {
            float xv[4], wv[4];
#pragma unroll
            for (int i = 0; i < 4; i++) xv[i] = xs[ty * 4 + i][kk];
#pragma unroll
            for (int j = 0; j < 4; j++) wv[j] = ws[tx * 4 + j][kk];
#pragma unroll
            for (int i = 0; i < 4; i++)
#pragma unroll
                for (int j = 0; j < 4; j++) acc[i][j] += xv[i] * wv[j];
        }
        __syncthreads();
    }

#pragma unroll
    for (int i = 0; i < 4; i++) {
        int row = rowBase + ty * 4 + i;
#pragma unroll
        for (int j = 0; j < 4; j++) {
            int col = colBase + tx * 4 + j;
            float v = acc[i][j] + bias[col];
            if (mode == 0) {
                int b = row >> 11;        // row / L
                int l = row & (L_ - 1);
                int head = col >> 5;
                int e = col & 31;
                Out[((size_t)((b * H_ + head) * L_ + l)) * h_ + e] = v;
            } else {
                Out[(size_t)row * D_ + col] = v;
            }
        }
    }
}

// =====================================================================
// K2: per-position: sim, normalize k/v in place, gate.  1 warp / pos.
// =====================================================================
__global__ void pointwise_kernel(const float* __restrict__ wg_w,
                                 const float* __restrict__ wg_b,
                                 const float* __restrict__ kv_scale,
                                 const float* __restrict__ qk_scale) {
    int warpId = threadIdx.x >> 5;
    int lane = threadIdx.x & 31;
    int pos = blockIdx.x * 4 + warpId;
    if (pos >= NPOS_) return;
    int head = (pos >> 11) & (H_ - 1);

    size_t base = (size_t)pos * h_ + lane;
    float q = g_Q[base];
    float k = g_K[base];
    float v = g_V[base];

    float sim = warpSum(q * k) * qk_scale[head];

    float kn = sqrtf(warpSum(k * k));
    k = k / fmaxf(kn, 1e-12f);
    float vn = sqrtf(warpSum(v * v));
    v = v / fmaxf(vn, 1e-12f);
    g_K[base] = k;
    g_V[base] = v;

    // gate logit = sum_{d,e} v_d * (W[d,e]*Skv[d,e]) * k_e ; lane = d
    const float* Wrow = wg_w + lane * h_;
    const float* Srow = kv_scale + (size_t)head * h_ * h_ + lane * h_;
    float inner = 0.f;
#pragma unroll
    for (int e = 0; e < 32; e++) {
        float ke = __shfl_sync(0xffffffffu, k, e);
        inner += Wrow[e] * Srow[e] * ke;
    }
    float logit = warpSum(v * inner) + wg_b[0];
    float r = fmaxf(logit, 0.f);
    float g = r * r + EPS_;

    if (lane == 0) {
        g_sim[pos] = sim;
        g_gate[pos] = g;
    }
}

// =====================================================================
// K3: per-chunk partials: Sdelta[32x32], gsum, (mloc, sloc)
// grid = BH*NC = 256 blocks, 256 threads
// =====================================================================
__global__ void chunk_partial_kernel(const float* __restrict__ kv_scale) {
    __shared__ float ks[C_][33];
    __shared__ float vs[C_][33];
    __shared__ float gsh[C_];
    __shared__ float simsh[C_];

    int c = blockIdx.x & (NC_ - 1);
    int bh = blockIdx.x >> 4;
    int head = bh & (H_ - 1);
    int base = bh * L_ + c * C_;

    for (int i = threadIdx.x; i < C_ * h_; i += 256) {
        int l = i >> 5, d = i & 31;
        ks[l][d] = g_K[(size_t)(base + l) * h_ + d];
        vs[l][d] = g_V[(size_t)(base + l) * h_ + d];
    }
    for (int i = threadIdx.x; i < C_; i += 256) {
        gsh[i] = g_gate[base + i];
        simsh[i] = g_sim[base + i];
    }
    __syncthreads();

    // Sdelta[d][e] = sum_i g_i * v[i][d] * k[i][e]; warp w: e=lane, d = w+8j
    int lane = threadIdx.x & 31;
    int w = threadIdx.x >> 5;
    float acc[4] = {0.f, 0.f, 0.f, 0.f};
    for (int i = 0; i < C_; i++) {
        float gk = gsh[i] * ks[i][lane];
#pragma unroll
        for (int j = 0; j < 4; j++) acc[j] += vs[i][w + 8 * j] * gk;
    }
    size_t sbase = (size_t)(bh * NC_ + c) * (h_ * h_);
#pragma unroll
    for (int j = 0; j < 4; j++) {
        int d = w + 8 * j;
        float sc = kv_scale[(size_t)head * 1024 + d * 32 + lane];
        g_Sdelta[sbase + d * 32 + lane] = acc[j] * sc;
    }

    // scalar reductions with warp 0
    if (threadIdx.x < 32) {
        float lm = -INFINITY, lg = 0.f;
#pragma unroll
        for (int j = 0; j < 4; j++) {
            lm = fmaxf(lm, simsh[lane + 32 * j]);
            lg += gsh[lane + 32 * j];
        }
        float mloc = warpMax(lm);
        float ls = 0.f;
#pragma unroll
        for (int j = 0; j < 4; j++) ls += expf(simsh[lane + 32 * j] - mloc);
        float sloc = warpSum(ls);
        float gsum = warpSum(lg);
        if (lane == 0) {
            int id = bh * NC_ + c;
            g_mloc[id] = mloc;
            g_sloc[id] = sloc;
            g_gsum[id] = gsum;
        }
    }
}

// =====================================================================
// K4: sequential exclusive scan over chunks. grid = BH = 16 blocks.
// =====================================================================
__global__ void chunk_scan_kernel() {
    int bh = blockIdx.x;
    int t = threadIdx.x;  // 256
    float acc[4] = {0.f, 0.f, 0.f, 0.f};
    for (int c = 0; c < NC_; c++) {
        size_t idx = (size_t)(bh * NC_ + c) * (h_ * h_);
#pragma unroll
        for (int j = 0; j < 4; j++) {
            g_Sprefix[idx + t + 256 * j] = acc[j];
            acc[j] += g_Sdelta[idx + t + 256 * j];
        }
    }
    if (t == 0) {
        float m = -INFINITY, s = 0.f, g = 0.f;
        for (int c = 0; c < NC_; c++) {
            int id = bh * NC_ + c;
            g_mpre[id] = m;
            g_spre[id] = s;
            g_gpre[id] = g;
            float mc = g_mloc[id], sc = g_sloc[id];
            float mn = fmaxf(m, mc);
            s = s * expf(m - mn) + sc * expf(mc - mn);
            m = mn;
            g += g_gsum[id];
        }
    }
}

// =====================================================================
// K5: chunk output. grid = BH*NC = 256 blocks, 256 threads, dyn smem.
// =====================================================================
__global__ void chunk_output_kernel() {
    extern __shared__ float sm5[];
    float* qs = sm5;                   // 128*33
    float* ks = qs + C_ * 33;          // 128*33
    float* vs = ks + C_ * 33;          // 128*33
    float* S0 = vs + C_ * 33;          // 32*33
    float* gsh = S0 + 32 * 33;         // 128
    float* simsh = gsh + C_;           // 128
    float* gcum = simsh + C_;          // 128
    float* msm = gcum + C_;            // 128
    float* ssm = msm + C_;             // 128

    int c = blockIdx.x & (NC_ - 1);
    int bh = blockIdx.x >> 4;
    int head = bh & (H_ - 1);
    int b = bh >> 3;
    int base = bh * L_ + c * C_;
    int t = threadIdx.x;

    for (int i = t; i < C_ * h_; i += 256) {
        int l = i >> 5, d = i & 31;
        qs[l * 33 + d] = g_Q[(size_t)(base + l) * h_ + d];
        ks[l * 33 + d] = g_K[(size_t)(base + l) * h_ + d];
        vs[l * 33 + d] = g_V[(size_t)(base + l) * h_ + d];
    }
    size_t sbase = (size_t)(bh * NC_ + c) * (h_ * h_);
    for (int i = t; i < h_ * h_; i += 256) {
        int d = i >> 5, e = i & 31;
        S0[d * 33 + e] = g_Sprefix[sbase + i];
    }
    for (int i = t; i < C_; i += 256) {
        float gv = g_gate[base + i];
        float sv = g_sim[base + i];
        gsh[i] = gv;
        simsh[i] = sv;
        gcum[i] = gv;
        msm[i] = sv;
        ssm[i] = 1.f;
    }
    __syncthreads();

    // Hillis-Steele inclusive scans over 128 elements (threads 0..127 own data)
    for (int off = 1; off < C_; off <<= 1) {
        float ga = 0.f, m2 = 0.f, s2 = 0.f;
        bool rd = (t < C_) && (t >= off);
        if (rd) {
            ga = gcum[t - off];
            m2 = msm[t - off];
            s2 = ssm[t - off];
        }
        __syncthreads();
        if (rd) {
            gcum[t] += ga;
            float m1 = msm[t], s1 = ssm[t];
            float mn = fmaxf(m1, m2);
            ssm[t] = s1 * expf(m1 - mn) + s2 * expf(m2 - mn);
            msm[t] = mn;
        }
        __syncthreads();
    }

    int id = bh * NC_ + c;
    float m0 = g_mpre[id], s0 = g_spre[id], g0 = g_gpre[id];

    // thread pair per row l; each handles 16 output columns
    int l = t >> 1;
    int half = t & 1;
    int eb = half * 16;

    float acc[16];
#pragma unroll
    for (int j = 0; j < 16; j++) acc[j] = 0.f;

    // Part A: q_l @ S0
#pragma unroll 8
    for (int d = 0; d < 32; d++) {
        float qv = qs[l * 33 + d];
#pragma unroll
        for (int j = 0; j < 16; j++) acc[j] += qv * S0[d * 33 + eb + j];
    }

    // Part B: causal intra-chunk. Pair (t, t^1) shares l; shfl-combine dot halves.
    unsigned pmask = 3u << (t & 30);
    for (int i = 0; i <= l; i++) {
        float p = 0.f;
#pragma unroll
        for (int dd = 0; dd < 16; dd++)
            p += qs[l * 33 + eb + dd] * vs[i * 33 + eb + dd];
        p += __shfl_xor_sync(pmask, p, 1);
        p *= gsh[i];
#pragma unroll
        for (int j = 0; j < 16; j++) acc[j] += p * ks[i * 33 + eb + j];
    }

    // final scaling
    float ml = msm[l], sl = ssm[l];
    float mn = fmaxf(m0, ml);
    float sfull = s0 * expf(m0 - mn) + sl * expf(ml - mn);
    float w = expf(simsh[l] - mn) / (sfull + EPS_);
    float silu = w / (1.f + expf(-w));
    float gc = gcum[l] + g0;
    float factor = (1.f + silu) / (gc + EPS_);

    int lg = c * C_ + l;
    size_t obase = ((size_t)b * L_ + lg) * D_ + head * h_ + eb;
#pragma unroll
    for (int j = 0; j < 16; j++) g_ctxt[obase + j] = acc[j] * factor;
}

// =====================================================================
// launch
// =====================================================================
extern "C" void kernel_launch(void* const* d_in, const int* in_sizes, int n_in,
                              void* d_out, int out_size) {
    const float* x = (const float*)d_in[0];
    const float* wq_w = (const float*)d_in[1];
    const float* wq_b = (const float*)d_in[2];
    const float* wk_w = (const float*)d_in[3];
    const float* wk_b = (const float*)d_in[4];
    const float* wv_w = (const float*)d_in[5];
    const float* wv_b = (const float*)d_in[6];
    const float* wo_w = (const float*)d_in[7];
    const float* wo_b = (const float*)d_in[8];
    const float* wg_w = (const float*)d_in[9];
    const float* wg_b = (const float*)d_in[10];
    const float* kv_scale = (const float*)d_in[11];
    const float* qk_scale = (const float*)d_in[12];
    float* out = (float*)d_out;

    float* Qp; cudaGetSymbolAddress((void**)&Qp, g_Q);
    float* Kp; cudaGetSymbolAddress((void**)&Kp, g_K);
    float* Vp; cudaGetSymbolAddress((void**)&Vp, g_V);
    float* Cp; cudaGetSymbolAddress((void**)&Cp, g_ctxt);

    dim3 gg(B_ * L_ / 64, D_ / 64);

    gemm_bias_kernel<<<gg, 256>>>(x, wq_w, wq_b, Qp, 0);
    gemm_bias_kernel<<<gg, 256>>>(x, wk_w, wk_b, Kp, 0);
    gemm_bias_kernel<<<gg, 256>>>(x, wv_w, wv_b, Vp, 0);

    pointwise_kernel<<<NPOS_ / 4, 128>>>(wg_w, wg_b, kv_scale, qk_scale);

    chunk_partial_kernel<<<BH_ * NC_, 256>>>(kv_scale);
    chunk_scan_kernel<<<BH_, 256>>>();

    const int smem5 = (3 * C_ * 33 + 32 * 33 + 5 * C_) * (int)sizeof(float);
    static bool attr_set = false;
    cudaFuncSetAttribute(chunk_output_kernel,
                         cudaFuncAttributeMaxDynamicSharedMemorySize, smem5);
    (void)attr_set;
    chunk_output_kernel<<<BH_ * NC_, 256, smem5>>>();

    gemm_bias_kernel<<<gg, 256>>>(Cp, wo_w, wo_b, out, 1);
}

// round 2
// speedup vs baseline: 2.1335x; 2.1335x over previous
#include <cuda_runtime.h>
#include <cuda_bf16.h>
#include <math.h>

// Problem constants
#define B_  2
#define L_  2048
#define D_  256
#define H_  8
#define h_  32
#define C_  128           // chunk size
#define NC_ (L_ / C_)     // 16 chunks per (b,h)
#define BH_ (B_ * H_)     // 16
#define NPOS_ (BH_ * L_)  // 32768
#define EPS_ 1e-5f

// -------- scratch (device globals, no allocation) --------
__device__ float g_Q[NPOS_ * h_];      // [B,H,L,h]
__device__ float g_K[NPOS_ * h_];
__device__ float g_V[NPOS_ * h_];
__device__ float g_sim[NPOS_];
__device__ float g_gate[NPOS_];
__device__ float g_M[H_ * h_ * h_];    // per-head gate matrix W∘kv_scale
__device__ float g_Sdelta[BH_ * NC_ * h_ * h_];
__device__ float g_Sprefix[BH_ * NC_ * h_ * h_];
__device__ float g_gsum[BH_ * NC_];
__device__ float g_mloc[BH_ * NC_];
__device__ float g_sloc[BH_ * NC_];
__device__ float g_gpre[BH_ * NC_];
__device__ float g_mpre[BH_ * NC_];
__device__ float g_spre[BH_ * NC_];
__device__ float g_ctxt[B_ * L_ * D_];  // [B,L,D]

// -------- helpers --------
__device__ __forceinline__ float warpSum(float v) {
#pragma unroll
    for (int o = 16; o > 0; o >>= 1) v += __shfl_xor_sync(0xffffffffu, v, o);
    return v;
}
__device__ __forceinline__ float warpMax(float v) {
#pragma unroll
    for (int o = 16; o > 0; o >>= 1) v = fmaxf(v, __shfl_xor_sync(0xffffffffu, v, o));
    return v;
}

// =====================================================================
// K0: precompute gate matrix M[head][d][e] = wg_w[d*32+e]*kv_scale[head,d,e]
// =====================================================================
__global__ void gate_mat_kernel(const float* __restrict__ wg_w,
                                const float* __restrict__ kv_scale) {
    int i = blockIdx.x * 256 + threadIdx.x;
    if (i < H_ * h_ * h_) g_M[i] = wg_w[i & 1023] * kv_scale[i];
}

// =====================================================================
// K1/K6: tiled fp32 GEMM:  Out[n,o] = sum_i X[n,i]*W[o,i] + bias[o]
// mode 0: scatter to [B,H,L,h] layout (for q/k/v). mode 1: row-major.
// M=4096, N=256, K=256. Tile 64x64, K-step 32, 256 threads, 4x4/thread.
// =====================================================================
__global__ void gemm_bias_kernel(const float* __restrict__ X,
                                 const float* __restrict__ W,
                                 const float* __restrict__ bias,
                                 float* __restrict__ Out, int mode) {
    __shared__ float xs[64][33];
    __shared__ float ws[64][33];
    const int tx = threadIdx.x & 15;
    const int ty = threadIdx.x >> 4;
    const int rowBase = blockIdx.x * 64;
    const int colBase = blockIdx.y * 64;

    float acc[4][4];
#pragma unroll
    for (int i = 0; i < 4; i++)
#pragma unroll
        for (int j = 0; j < 4; j++) acc[i][j] = 0.f;

    for (int k0 = 0; k0 < D_; k0 += 32) {
#pragma unroll
        for (int i = threadIdx.x; i < 64 * 32; i += 256) {
            int m = i >> 5, kk = i & 31;
            xs[m][kk] = X[(size_t)(rowBase + m) * D_ + k0 + kk];
            ws[m][kk] = W[(size_t)(colBase + m) * D_ + k0 + kk];
        }
        __syncthreads();
#pragma unroll
        for (int kk = 0; kk < 32; kk++) {
            float xv[4], wv[4];
#pragma unroll
            for (int i = 0; i < 4; i++) xv[i] = xs[ty * 4 + i][kk];
#pragma unroll
            for (int j = 0; j < 4; j++) wv[j] = ws[tx * 4 + j][kk];
#pragma unroll
            for (int i = 0; i < 4; i++)
#pragma unroll
                for (int j = 0; j < 4; j++) acc[i][j] += xv[i] * wv[j];
        }
        __syncthreads();
    }

#pragma unroll
    for (int i = 0; i < 4; i++) {
        int row = rowBase + ty * 4 + i;
#pragma unroll
        for (int j = 0; j < 4; j++) {
            int col = colBase + tx * 4 + j;
            float v = acc[i][j] + bias[col];
            if (mode == 0) {
                int b = row >> 11;        // row / L
                int l = row & (L_ - 1);
                int head = col >> 5;
                int e = col & 31;
                Out[((size_t)((b * H_ + head) * L_ + l)) * h_ + e] = v;
            } else {
                Out[(size_t)row * D_ + col] = v;
            }
        }
    }
}

// =====================================================================
// K2 (fused): per-position sim/normalize/gate + per-chunk partials.
// grid = BH*NC = 256 blocks, 256 threads (8 warps). Warp w owns
// positions l = w*16 .. w*16+15 for the pointwise stage.
// =====================================================================
__global__ void chunk_fused_kernel(const float* __restrict__ kv_scale,
                                   const float* __restrict__ qk_scale,
                                   const float* __restrict__ wg_b) {
    __shared__ float ks[C_][33];
    __shared__ float vs[C_][33];
    __shared__ float gsh[C_];
    __shared__ float simsh[C_];
    __shared__ float msh[h_ * 33];

    int c = blockIdx.x & (NC_ - 1);
    int bh = blockIdx.x >> 4;
    int head = bh & (H_ - 1);
    int base = bh * L_ + c * C_;
    int lane = threadIdx.x & 31;
    int w = threadIdx.x >> 5;

    // stage gate matrix into padded smem
    for (int i = threadIdx.x; i < h_ * h_; i += 256)
        msh[(i >> 5) * 33 + (i & 31)] = g_M[head * (h_ * h_) + i];
    __syncthreads();

    // lane d holds row d of M in registers (conflict-free padded reads)
    float Mreg[32];
#pragma unroll
    for (int e = 0; e < 32; e++) Mreg[e] = msh[lane * 33 + e];

    float qksc = qk_scale[head];
    float gb = wg_b[0];

    // ---- pointwise stage: 16 positions per warp ----
#pragma unroll 4
    for (int j = 0; j < 16; j++) {
        int l = w * 16 + j;
        size_t gidx = (size_t)(base + l) * h_ + lane;
        float q = g_Q[gidx];
        float k = g_K[gidx];
        float v = g_V[gidx];

        float sim = warpSum(q * k) * qksc;
        float kn = sqrtf(warpSum(k * k));
        k = k / fmaxf(kn, 1e-12f);
        float vn = sqrtf(warpSum(v * v));
        v = v / fmaxf(vn, 1e-12f);

        // gate logit = sum_d v_d * sum_e M[d][e] * k_e
        float inner = 0.f;
#pragma unroll
        for (int e = 0; e < 32; e++)
            inner = fmaf(Mreg[e], __shfl_sync(0xffffffffu, k, e), inner);
        float logit = warpSum(v * inner) + gb;
        float r = fmaxf(logit, 0.f);
        float g = r * r + EPS_;

        ks[l][lane] = k;
        vs[l][lane] = v;
        g_K[gidx] = k;
        g_V[gidx] = v;
        if (lane == 0) {
            gsh[l] = g;
            simsh[l] = sim;
            g_gate[base + l] = g;
            g_sim[base + l] = sim;
        }
    }
    __syncthreads();

    // ---- Sdelta[d][e] = sum_i g_i * v[i][d] * k[i][e]; warp w: e=lane, d=w+8j
    float acc[4] = {0.f, 0.f, 0.f, 0.f};
    for (int i = 0; i < C_; i++) {
        float gk = gsh[i] * ks[i][lane];
#pragma unroll
        for (int j = 0; j < 4; j++) acc[j] += vs[i][w + 8 * j] * gk;
    }
    size_t sbase = (size_t)(bh * NC_ + c) * (h_ * h_);
#pragma unroll
    for (int j = 0; j < 4; j++) {
        int d = w + 8 * j;
        float sc = kv_scale[(size_t)head * (h_ * h_) + d * 32 + lane];
        g_Sdelta[sbase + d * 32 + lane] = acc[j] * sc;
    }

    // ---- scalar reductions (warp 0) ----
    if (threadIdx.x < 32) {
        float lm = -INFINITY, lg = 0.f;
#pragma unroll
        for (int j = 0; j < 4; j++) {
            lm = fmaxf(lm, simsh[lane + 32 * j]);
            lg += gsh[lane + 32 * j];
        }
        float mloc = warpMax(lm);
        float ls = 0.f;
#pragma unroll
        for (int j = 0; j < 4; j++) ls += expf(simsh[lane + 32 * j] - mloc);
        float sloc = warpSum(ls);
        float gsum = warpSum(lg);
        if (lane == 0) {
            int id = bh * NC_ + c;
            g_mloc[id] = mloc;
            g_sloc[id] = sloc;
            g_gsum[id] = gsum;
        }
    }
}

// =====================================================================
// K4: sequential exclusive scan over chunks. grid = BH = 16 blocks.
// =====================================================================
__global__ void chunk_scan_kernel() {
    int bh = blockIdx.x;
    int t = threadIdx.x;  // 256
    float acc[4] = {0.f, 0.f, 0.f, 0.f};
    for (int c = 0; c < NC_; c++) {
        size_t idx = (size_t)(bh * NC_ + c) * (h_ * h_);
#pragma unroll
        for (int j = 0; j < 4; j++) {
            g_Sprefix[idx + t + 256 * j] = acc[j];
            acc[j] += g_Sdelta[idx + t + 256 * j];
        }
    }
    if (t == 0) {
        float m = -INFINITY, s = 0.f, g = 0.f;
        for (int c = 0; c < NC_; c++) {
            int id = bh * NC_ + c;
            g_mpre[id] = m;
            g_spre[id] = s;
            g_gpre[id] = g;
            float mc = g_mloc[id], sc = g_sloc[id];
            float mn = fmaxf(m, mc);
            s = s * expf(m - mn) + sc * expf(mc - mn);
            m = mn;
            g += g_gsum[id];
        }
    }
}

// =====================================================================
// K5: chunk output. grid = BH*NC = 256 blocks, 256 threads, dyn smem.
// =====================================================================
__global__ void chunk_output_kernel() {
    extern __shared__ float sm5[];
    float* qs = sm5;                   // 128*33
    float* ks = qs + C_ * 33;          // 128*33
    float* vs = ks + C_ * 33;          // 128*33
    float* S0 = vs + C_ * 33;          // 32*33
    float* gsh = S0 + 32 * 33;         // 128
    float* simsh = gsh + C_;           // 128
    float* gcum = simsh + C_;          // 128
    float* msm = gcum + C_;            // 128
    float* ssm = msm + C_;             // 128

    int c = blockIdx.x & (NC_ - 1);
    int bh = blockIdx.x >> 4;
    int head = bh & (H_ - 1);
    int b = bh >> 3;
    int base = bh * L_ + c * C_;
    int t = threadIdx.x;

    for (int i = t; i < C_ * h_; i += 256) {
        int l = i >> 5, d = i & 31;
        qs[l * 33 + d] = g_Q[(size_t)(base + l) * h_ + d];
        ks[l * 33 + d] = g_K[(size_t)(base + l) * h_ + d];
        vs[l * 33 + d] = g_V[(size_t)(base + l) * h_ + d];
    }
    size_t sbase = (size_t)(bh * NC_ + c) * (h_ * h_);
    for (int i = t; i < h_ * h_; i += 256) {
        int d = i >> 5, e = i & 31;
        S0[d * 33 + e] = g_Sprefix[sbase + i];
    }
    for (int i = t; i < C_; i += 256) {
        float gv = g_gate[base + i];
        float sv = g_sim[base + i];
        gsh[i] = gv;
        simsh[i] = sv;
        gcum[i] = gv;
        msm[i] = sv;
        ssm[i] = 1.f;
    }
    __syncthreads();

    // Hillis-Steele inclusive scans over 128 elements (threads 0..127 own data)
    for (int off = 1; off < C_; off <<= 1) {
        float ga = 0.f, m2 = 0.f, s2 = 0.f;
        bool rd = (t < C_) && (t >= off);
        if (rd) {
            ga = gcum[t - off];
            m2 = msm[t - off];
            s2 = ssm[t - off];
        }
        __syncthreads();
        if (rd) {
            gcum[t] += ga;
            float m1 = msm[t], s1 = ssm[t];
            float mn = fmaxf(m1, m2);
            ssm[t] = s1 * expf(m1 - mn) + s2 * expf(m2 - mn);
            msm[t] = mn;
        }
        __syncthreads();
    }

    int id = bh * NC_ + c;
    float m0 = g_mpre[id], s0 = g_spre[id], g0 = g_gpre[id];

    // thread pair per row l; each handles 16 output columns
    int l = t >> 1;
    int half = t & 1;
    int eb = half * 16;

    float acc[16];
#pragma unroll
    for (int j = 0; j < 16; j++) acc[j] = 0.f;

    // Part A: q_l @ S0
#pragma unroll 8
    for (int d = 0; d < 32; d++) {
        float qv = qs[l * 33 + d];
#pragma unroll
        for (int j = 0; j < 16; j++) acc[j] += qv * S0[d * 33 + eb + j];
    }

    // Part B: causal intra-chunk. Pair (t, t^1) shares l; shfl-combine dot halves.
    unsigned pmask = 3u << (t & 30);
    for (int i = 0; i <= l; i++) {
        float p = 0.f;
#pragma unroll
        for (int dd = 0; dd < 16; dd++)
            p += qs[l * 33 + eb + dd] * vs[i * 33 + eb + dd];
        p += __shfl_xor_sync(pmask, p, 1);
        p *= gsh[i];
#pragma unroll
        for (int j = 0; j < 16; j++) acc[j] += p * ks[i * 33 + eb + j];
    }

    // final scaling
    float ml = msm[l], sl = ssm[l];
    float mn = fmaxf(m0, ml);
    float sfull = s0 * expf(m0 - mn) + sl * expf(ml - mn);
    float w = expf(simsh[l] - mn) / (sfull + EPS_);
    float silu = w / (1.f + expf(-w));
    float gc = gcum[l] + g0;
    float factor = (1.f + silu) / (gc + EPS_);

    int lg = c * C_ + l;
    size_t obase = ((size_t)b * L_ + lg) * D_ + head * h_ + eb;
#pragma unroll
    for (int j = 0; j < 16; j++) g_ctxt[obase + j] = acc[j] * factor;
}

// =====================================================================
// launch
// =====================================================================
extern "C" void kernel_launch(void* const* d_in, const int* in_sizes, int n_in,
                              void* d_out, int out_size) {
    const float* x = (const float*)d_in[0];
    const float* wq_w = (const float*)d_in[1];
    const float* wq_b = (const float*)d_in[2];
    const float* wk_w = (const float*)d_in[3];
    const float* wk_b = (const float*)d_in[4];
    const float* wv_w = (const float*)d_in[5];
    const float* wv_b = (const float*)d_in[6];
    const float* wo_w = (const float*)d_in[7];
    const float* wo_b = (const float*)d_in[8];
    const float* wg_w = (const float*)d_in[9];
    const float* wg_b = (const float*)d_in[10];
    const float* kv_scale = (const float*)d_in[11];
    const float* qk_scale = (const float*)d_in[12];
    float* out = (float*)d_out;

    float* Qp; cudaGetSymbolAddress((void**)&Qp, g_Q);
    float* Kp; cudaGetSymbolAddress((void**)&Kp, g_K);
    float* Vp; cudaGetSymbolAddress((void**)&Vp, g_V);
    float* Cp; cudaGetSymbolAddress((void**)&Cp, g_ctxt);

    dim3 gg(B_ * L_ / 64, D_ / 64);

    gemm_bias_kernel<<<gg, 256>>>(x, wq_w, wq_b, Qp, 0);
    gemm_bias_kernel<<<gg, 256>>>(x, wk_w, wk_b, Kp, 0);
    gemm_bias_kernel<<<gg, 256>>>(x, wv_w, wv_b, Vp, 0);

    gate_mat_kernel<<<(H_ * h_ * h_ + 255) / 256, 256>>>(wg_w, kv_scale);

    chunk_fused_kernel<<<BH_ * NC_, 256>>>(kv_scale, qk_scale, wg_b);
    chunk_scan_kernel<<<BH_, 256>>>();

    const int smem5 = (3 * C_ * 33 + 32 * 33 + 5 * C_) * (int)sizeof(float);
    cudaFuncSetAttribute(chunk_output_kernel,
                         cudaFuncAttributeMaxDynamicSharedMemorySize, smem5);
    chunk_output_kernel<<<BH_ * NC_, 256, smem5>>>();

    gemm_bias_kernel<<<gg, 256>>>(Cp, wo_w, wo_b, out, 1);
}